// round 4
// baseline (speedup 1.0000x reference)
#include <cuda_runtime.h>
#include <cstdint>

#define N_TOK 8192
#define HID   8192
#define NG    16
#define NE    16

#define BM      32
#define BK      64
#define NSTAGE  (HID / BK)        // 128
#define NBUF    6

// per-warp stage region: X 32 tok x 32B = 1024B, W 8k x 64B = 512B
#define WARP_STAGE 1536
#define CTA_STAGE  (8 * WARP_STAGE)        // 12288
#define RING_BYTES (NBUF * CTA_STAGE)      // 73728 (dynamic smem)

typedef unsigned long long ull;

// ---------------- device scratch ----------------
__device__ float d_w1t[HID * NG];   // W1 transposed: [k][g], 64B rows
__device__ float d_gsum[NG];
__device__ float d_msum[NE];
__device__ int   d_gsel[N_TOK];
__device__ int   d_gcount[NG];
__device__ int   d_goff[NG];
__device__ int   d_gcur[NG];
__device__ int   d_perm[N_TOK];

// ---------------- helpers ----------------
__device__ __forceinline__ ull ffma2(ull a, ull b, ull c) {
    ull d;
    asm("fma.rn.f32x2 %0, %1, %2, %3;" : "=l"(d) : "l"(a), "l"(b), "l"(c));
    return d;
}
__device__ __forceinline__ ull dup2(float x) {
    ull d;
    asm("mov.b64 %0, {%1, %1};" : "=l"(d) : "f"(x));
    return d;
}
__device__ __forceinline__ float2 unpk(ull v) {
    float2 r;
    asm("mov.b64 {%0, %1}, %2;" : "=f"(r.x), "=f"(r.y) : "l"(v));
    return r;
}
__device__ __forceinline__ uint32_t s2u(const void* p) {
    return (uint32_t)__cvta_generic_to_shared(p);
}
__device__ __forceinline__ void cp16(uint32_t dst, const void* src) {
    asm volatile("cp.async.cg.shared.global [%0], [%1], 16;" :: "r"(dst), "l"(src));
}
#define CP_COMMIT() asm volatile("cp.async.commit_group;" ::: "memory")
#define CP_WAIT4()  asm volatile("cp.async.wait_group 4;" ::: "memory")
#define CP_WAIT0()  asm volatile("cp.async.wait_group 0;" ::: "memory")

// ============================================================
// Warp-private GEMM mainloop.
//   xsrc : this lane's X source base (token row + warp k-offset)
//   wsrc : this lane's W source base (k row + chunk), row stride 64B, +s*4096/stage
// Each warp owns k's [wid*8, wid*8+8) of every 64-k stage.
// Accumulators: acc[i][p] = tokens (tcol+8i), group pair (grow*8+2p, +1),
// partial over k % 16 == {wid*2+ksub mapping}.
// ============================================================
__device__ __forceinline__ void gemm_mainloop(char* sm, const char* xsrc,
                                              const char* wsrc, int tid,
                                              ull acc[4][4])
{
    const int wid  = tid >> 5, lane = tid & 31;
    const int tcol = lane & 7, grow = (lane >> 3) & 1, ksub = lane >> 4;
    const uint32_t wbase = s2u(sm) + wid * WARP_STAGE;
    const uint32_t xdst  = wbase + lane * 32;
    const uint32_t wdst  = wbase + 1024 + lane * 16;

#pragma unroll
    for (int i = 0; i < 4; i++)
#pragma unroll
        for (int p = 0; p < 4; p++) acc[i][p] = 0ULL;

#define WISSUE(s_) do {                                           \
        uint32_t _b = ((s_) % NBUF) * CTA_STAGE;                  \
        const char* _x = xsrc + (size_t)(s_) * 256;               \
        cp16(xdst + _b,      _x);                                 \
        cp16(xdst + _b + 16, _x + 16);                            \
        cp16(wdst + _b,      wsrc + (size_t)(s_) * 4096);         \
    } while (0)

    WISSUE(0); CP_COMMIT();
    WISSUE(1); CP_COMMIT();
    WISSUE(2); CP_COMMIT();
    WISSUE(3); CP_COMMIT();
    WISSUE(4); CP_COMMIT();

    for (int s = 0; s < NSTAGE; s++) {
        CP_WAIT4();
        const char* bb = sm + (s % NBUF) * CTA_STAGE + wid * WARP_STAGE;
        float4 xv[4];
#pragma unroll
        for (int i = 0; i < 4; i++)
            xv[i] = *(const float4*)(bb + (tcol + 8 * i) * 32 + ksub * 16);
#pragma unroll
        for (int j = 0; j < 4; j++) {
            const int kl = ksub * 4 + j;
            const char* wb = bb + 1024 + kl * 64 + grow * 32;
            ulonglong2 wv = *(const ulonglong2*)wb;
            ulonglong2 wu = *(const ulonglong2*)(wb + 16);
            ull w[4] = {wv.x, wv.y, wu.x, wu.y};
#pragma unroll
            for (int i = 0; i < 4; i++) {
                ull xd = dup2(reinterpret_cast<const float*>(&xv[i])[j]);
#pragma unroll
                for (int p = 0; p < 4; p++) acc[i][p] = ffma2(xd, w[p], acc[i][p]);
            }
        }
        if (s + 5 < NSTAGE) WISSUE(s + 5);
        CP_COMMIT();
    }
    CP_WAIT0();
#undef WISSUE
}

// Cross-warp reduction into red[32][17] (red aliases ring smem, after syncthreads)
__device__ __forceinline__ void reduce_acc(float* red, int tid, ull acc[4][4])
{
    const int lane = tid & 31, wid = tid >> 5;
    const int tcol = lane & 7, grow = (lane >> 3) & 1, ksub = lane >> 4;
    const int slice = wid * 2 + ksub;   // 0..15
    for (int q = 0; q < 16; q++) {
        if (slice == q) {
#pragma unroll
            for (int i = 0; i < 4; i++)
#pragma unroll
                for (int p = 0; p < 4; p++) {
                    float2 v = unpk(acc[i][p]);
                    const int t = tcol + 8 * i, g = grow * 8 + 2 * p;
                    if (q == 0) { red[t * 17 + g] = v.x; red[t * 17 + g + 1] = v.y; }
                    else        { red[t * 17 + g] += v.x; red[t * 17 + g + 1] += v.y; }
                }
        }
        __syncthreads();
    }
}

// ============================================================
// Prep: transpose W1 -> d_w1t[k][g]; zero accumulators
// ============================================================
__global__ void k_prep(const float* __restrict__ W1)
{
    const int k = blockIdx.x * 256 + threadIdx.x;
    float v[NG];
#pragma unroll
    for (int g = 0; g < NG; g++) v[g] = W1[(size_t)g * HID + k];
#pragma unroll
    for (int q = 0; q < 4; q++)
        *reinterpret_cast<float4*>(d_w1t + (size_t)k * NG + q * 4) =
            make_float4(v[q * 4], v[q * 4 + 1], v[q * 4 + 2], v[q * 4 + 3]);
    if (blockIdx.x == 0 && threadIdx.x < NG) {
        d_gsum[threadIdx.x] = 0.f;
        d_msum[threadIdx.x] = 0.f;
        d_gcount[threadIdx.x] = 0;
    }
}

// ============================================================
// Kernel 1: group-gate GEMM + softmax/argmax/sums/hist
// ============================================================
__global__ void __launch_bounds__(256, 2)
k_group_gemm(const float* __restrict__ X)
{
    extern __shared__ __align__(16) char sm[];
    __shared__ int shist[NG];

    const int tid = threadIdx.x, wid = tid >> 5, lane = tid & 31;
    if (tid < NG) shist[tid] = 0;

    const char* xsrc = (const char*)(X + (size_t)(blockIdx.x * BM + lane) * HID) + wid * 32;
    const char* wsrc = (const char*)d_w1t + wid * 512 + lane * 16;

    ull acc[4][4];
    gemm_mainloop(sm, xsrc, wsrc, tid, acc);
    __syncthreads();

    float* red = (float*)sm;
    reduce_acc(red, tid, acc);

    float* pb = (float*)(sm + 2560);    // [32][17]
    if (tid < BM) {
        float l[NG];
#pragma unroll
        for (int g = 0; g < NG; g++) l[g] = red[tid * 17 + g];
        float m = l[0];
        int gi = 0;
#pragma unroll
        for (int g = 1; g < NG; g++)
            if (l[g] > m) { m = l[g]; gi = g; }
        float p[NG], ss = 0.f;
#pragma unroll
        for (int g = 0; g < NG; g++) { p[g] = __expf(l[g] - m); ss += p[g]; }
        const float inv = 1.0f / ss;
#pragma unroll
        for (int g = 0; g < NG; g++) pb[tid * 17 + g] = p[g] * inv;
        d_gsel[blockIdx.x * BM + tid] = gi;
        atomicAdd(&shist[gi], 1);
    }
    __syncthreads();
    if (tid < NG) {
        float s = 0.f;
        for (int t = 0; t < BM; t++) s += pb[t * 17 + tid];
        atomicAdd(&d_gsum[tid], s);
        atomicAdd(&d_gcount[tid], shist[tid]);
    }
}

// ============================================================
// Sorting pipeline
// ============================================================
__global__ void k_prefix()
{
    if (threadIdx.x == 0) {
        int a = 0;
        for (int g = 0; g < NG; g++) { d_goff[g] = a; d_gcur[g] = a; a += d_gcount[g]; }
    }
}

__global__ void k_scatter()
{
    __shared__ int cnt[NG], base[NG];
    const int tid = threadIdx.x;
    if (tid < NG) cnt[tid] = 0;
    __syncthreads();
    const int n = blockIdx.x * blockDim.x + tid;
    const int g = d_gsel[n];
    const int r = atomicAdd(&cnt[g], 1);
    __syncthreads();
    if (tid < NG) base[tid] = atomicAdd(&d_gcur[tid], cnt[tid]);
    __syncthreads();
    d_perm[base[g] + r] = n;
}

// ============================================================
// Kernel 2: mini-gate GEMM (gathered rows) + top-4 epilogue
// ============================================================
__global__ void __launch_bounds__(256, 2)
k_mini_gemm(const float* __restrict__ X, const float* __restrict__ WM,
            float* __restrict__ out)
{
    const int g     = blockIdx.y;
    const int cnt   = d_gcount[g];
    const int start = blockIdx.x * BM;
    if (start >= cnt) return;
    const int nvalid = min(BM, cnt - start);
    const int off    = d_goff[g];

    extern __shared__ __align__(16) char sm[];
    __shared__ int rows_s[BM];

    const int tid = threadIdx.x, wid = tid >> 5, lane = tid & 31;
    if (tid < BM) {
        int ix = start + tid;
        if (ix >= cnt) ix = cnt - 1;    // clamp: duplicate rows, discarded
        rows_s[tid] = d_perm[off + ix];
    }
    __syncthreads();

    const char* xsrc = (const char*)(X + (size_t)rows_s[lane] * HID) + wid * 32;
    // WM[g] is [H][16] k-major, 64B rows — used directly
    const char* wsrc = (const char*)(WM + (size_t)g * HID * NE) + wid * 512 + lane * 16;

    ull acc[4][4];
    gemm_mainloop(sm, xsrc, wsrc, tid, acc);
    __syncthreads();

    float* red = (float*)sm;
    reduce_acc(red, tid, acc);

    float* pb = (float*)(sm + 2560);    // [32][17]
    if (tid < BM) {
        const bool valid = (tid < nvalid);
        float l[NE];
#pragma unroll
        for (int e = 0; e < NE; e++) l[e] = red[tid * 17 + e];
        float m = l[0];
#pragma unroll
        for (int e = 1; e < NE; e++) m = fmaxf(m, l[e]);
        float ex[NE], ss = 0.f;
#pragma unroll
        for (int e = 0; e < NE; e++) { ex[e] = __expf(l[e] - m); ss += ex[e]; }
        const float inv = 1.0f / ss;
#pragma unroll
        for (int e = 0; e < NE; e++) pb[tid * 17 + e] = valid ? ex[e] * inv : 0.f;

        if (valid) {
            // top-4 by logit; strict > keeps lowest index on ties (lax.top_k order)
            float cur[NE];
#pragma unroll
            for (int e = 0; e < NE; e++) cur[e] = l[e];
            int eidx[4];
            float ev[4], den = 0.f;
#pragma unroll
            for (int j = 0; j < 4; j++) {
                float best = -3.4e38f;
                int bi = 0;
#pragma unroll
                for (int e = 0; e < NE; e++)
                    if (cur[e] > best) { best = cur[e]; bi = e; }
                cur[bi] = -3.4e38f;
                eidx[j] = bi;
                ev[j] = ex[bi];
                den += ex[bi];
            }
            // group prob cancels in normalization: final = ex_j / sum(top4 ex)
            const float invd = 1.0f / den;
            const int n = rows_s[tid];
#pragma unroll
            for (int j = 0; j < 4; j++) {
                out[(size_t)n * 4 + j] = ev[j] * invd;
                out[(size_t)N_TOK * 4 + (size_t)n * 4 + j] = (float)(g * NE + eidx[j]);
            }
        }
    }
    __syncthreads();
    if (tid < NE) {
        float s = 0.f;
        for (int t = 0; t < BM; t++) s += pb[t * 17 + tid];
        atomicAdd(&d_msum[tid], s);
    }
}

// ============================================================
// Finalize: aux loss
// ============================================================
__global__ void k_final(float* __restrict__ out, int out_size)
{
    if (threadIdx.x == 0) {
        float a = 0.f;
        for (int i = 0; i < NG; i++) { float x = d_gsum[i] / (float)N_TOK; a += x * x; }
        for (int i = 0; i < NE; i++) { float x = d_msum[i] / (float)N_TOK; a += x * x; }
        out[out_size - 1] = a;
    }
}

// ============================================================
extern "C" void kernel_launch(void* const* d_in, const int* in_sizes, int n_in,
                              void* d_out, int out_size)
{
    const float* X  = (const float*)d_in[0];  // hidden_states [N, H]
    const float* W1 = (const float*)d_in[1];  // group_gate_w  [16, H]
    const float* WM = (const float*)d_in[2];  // mini_gates    [16, H, 16]
    float* out = (float*)d_out;               // [probs N*4 | indices N*4 | aux]

    cudaFuncSetAttribute(k_group_gemm, cudaFuncAttributeMaxDynamicSharedMemorySize, RING_BYTES);
    cudaFuncSetAttribute(k_mini_gemm,  cudaFuncAttributeMaxDynamicSharedMemorySize, RING_BYTES);

    k_prep<<<HID / 256, 256>>>(W1);
    k_group_gemm<<<N_TOK / BM, 256, RING_BYTES>>>(X);
    k_prefix<<<1, 32>>>();
    k_scatter<<<N_TOK / 256, 256>>>();
    k_mini_gemm<<<dim3(N_TOK / BM, NG), 256, RING_BYTES>>>(X, WM, out);
    k_final<<<1, 32>>>(out, out_size);
}